// round 14
// baseline (speedup 1.0000x reference)
#include <cuda_runtime.h>
#include <stdint.h>

// out[i,j] = 2*x[i,j] + 5 - (i+j), x: [8192, 8192] fp32.
//
// Flat-grid HBM-streaming kernel at the machine ceiling (~6.5 TB/s, ~81-82%
// of 8 TB/s spec; DRAM-pipe bound, compute <6%).
// Probe (last unexplored cell): THREADS=1024 x UNROLL=2 — combines the
// 1024-block extent advantage (best measured DRAM%: 82.9) with recovered
// occupancy (halved register staging vs 1024xU4's occ 67.7%). 32KB per-CTA
// extent, 16KB contiguous warp traffic per unroll step, 8192 blocks.

#define N_DIM 8192
#define M_DIM 8192
#define VEC_PER_ROW_LOG2 11             // 8192/4 = 2048 float4 per row
#define VEC_PER_ROW (1 << VEC_PER_ROW_LOG2)
#define UNROLL 2
#define THREADS 1024

__global__ __launch_bounds__(THREADS) void fused_affine_outer_kernel(
    const float4* __restrict__ x, float4* __restrict__ out)
{
    // Each block owns a contiguous chunk of UNROLL*THREADS vectors;
    // within each unroll step the warp's accesses are fully coalesced.
    unsigned int base = blockIdx.x * (THREADS * UNROLL) + threadIdx.x;

    float4 in[UNROLL];
#pragma unroll
    for (int k = 0; k < UNROLL; k++) {
        in[k] = __ldcs(&x[base + k * THREADS]);
    }

#pragma unroll
    for (int k = 0; k < UNROLL; k++) {
        unsigned int v  = base + k * THREADS;
        unsigned int i  = v >> VEC_PER_ROW_LOG2;          // row
        unsigned int j4 = (v & (VEC_PER_ROW - 1)) << 2;   // col of lane 0
        float b = 5.0f - (float)(i + j4);

        float4 o;
        o.x = fmaf(in[k].x, 2.0f, b);
        o.y = fmaf(in[k].y, 2.0f, b - 1.0f);
        o.z = fmaf(in[k].z, 2.0f, b - 2.0f);
        o.w = fmaf(in[k].w, 2.0f, b - 3.0f);
        __stcs(&out[v], o);
    }
}

extern "C" void kernel_launch(void* const* d_in, const int* in_sizes, int n_in,
                              void* d_out, int out_size)
{
    const float4* x = (const float4*)d_in[0];
    float4* out = (float4*)d_out;

    const unsigned int total_vec = (N_DIM * M_DIM) / 4;         // 16,777,216
    const unsigned int blocks = total_vec / (THREADS * UNROLL); // 8,192

    fused_affine_outer_kernel<<<blocks, THREADS>>>(x, out);
}

// round 15
// speedup vs baseline: 1.0254x; 1.0254x over previous
#include <cuda_runtime.h>
#include <stdint.h>

// out[i,j] = 2*x[i,j] + 5 - (i+j), x: [8192, 8192] fp32.
//
// FINAL KERNEL — flat-grid HBM stream at the machine ceiling:
// 6.45-6.52 TB/s (~81-82% of 8 TB/s spec), DRAM-pipe-bound, compute <6%,
// traffic minimal (1R+1W per element, fully-coalesced 128B transactions).
//
// Complete measured design space (14 rounds):
//   per-thread MLP: U1->82.2 | U4->81.7 (OPT) | U8->82.6 (occ drop) |
//                   U2@1024->84.1 (stores interleave into the read burst;
//                   L1 util 41->63%, DRAM 81.5->74.2%)
//   threads:  256->82.0 | 512->81.7 (OPT) | 1024->82.0
//   schedule: flat (OPT) | persistent 1-wave -> 92.9 (per-CTA loop
//             serializes next loads behind prior stores)
//   loads:    __ldcs (OPT) | __ldcg neutral (l1tex never binding at U4)
//   stores:   __stcs (OPT) | __stwt -> 82.9 (loses L2 write-combining)
// Six reproductions of this config: 81.73-82.14us (harness noise floor).
// TMA/smem/cluster cannot beat direct LDG/STG: B300 LTS cap (~6300 B/cyc)
// is path-independent (LDG.cv == TMA).
//
// Config: 512 threads, 4x front-batched float4 loads per thread (MLP=4),
// __ldcs/__stcs evict-first hints (zero reuse), exact-cover 8192-block grid.

#define N_DIM 8192
#define M_DIM 8192
#define VEC_PER_ROW_LOG2 11             // 8192/4 = 2048 float4 per row
#define VEC_PER_ROW (1 << VEC_PER_ROW_LOG2)
#define UNROLL 4
#define THREADS 512

__global__ __launch_bounds__(THREADS) void fused_affine_outer_kernel(
    const float4* __restrict__ x, float4* __restrict__ out)
{
    // Each block owns a contiguous chunk of UNROLL*THREADS vectors;
    // within each unroll step the warp's accesses are fully coalesced.
    unsigned int base = blockIdx.x * (THREADS * UNROLL) + threadIdx.x;

    float4 in[UNROLL];
#pragma unroll
    for (int k = 0; k < UNROLL; k++) {
        in[k] = __ldcs(&x[base + k * THREADS]);
    }

#pragma unroll
    for (int k = 0; k < UNROLL; k++) {
        unsigned int v  = base + k * THREADS;
        unsigned int i  = v >> VEC_PER_ROW_LOG2;          // row
        unsigned int j4 = (v & (VEC_PER_ROW - 1)) << 2;   // col of lane 0
        float b = 5.0f - (float)(i + j4);

        float4 o;
        o.x = fmaf(in[k].x, 2.0f, b);
        o.y = fmaf(in[k].y, 2.0f, b - 1.0f);
        o.z = fmaf(in[k].z, 2.0f, b - 2.0f);
        o.w = fmaf(in[k].w, 2.0f, b - 3.0f);
        __stcs(&out[v], o);
    }
}

extern "C" void kernel_launch(void* const* d_in, const int* in_sizes, int n_in,
                              void* d_out, int out_size)
{
    const float4* x = (const float4*)d_in[0];
    float4* out = (float4*)d_out;

    const unsigned int total_vec = (N_DIM * M_DIM) / 4;         // 16,777,216
    const unsigned int blocks = total_vec / (THREADS * UNROLL); // 8,192

    fused_affine_outer_kernel<<<blocks, THREADS>>>(x, out);
}